// round 15
// baseline (speedup 1.0000x reference)
#include <cuda_runtime.h>

// StatelessConvLIF: fused 3x3 SAME conv (fp32) + LIF scan over T=8.
// x: [8,16,64,64,64] fp32, W: [128,64,3,3] fp32, out spikes: [8,16,128,64,64] fp32.
//
// R15: single-variable round. Keep R14's 3-stage cp.async ring with
// wait_group 1 (the component that won: chunk-boundary load waits gone);
// revert the channel loop to unroll 1 (R14's unroll 2 raised alu 29.7->36.8%
// and dropped fma 50.1->46.2% -- pure overhead). Conv accumulation order is
// bit-identical to R8/R10/R14 -> rel_err must stay 7.0777e-4.

#define THREADS 256
#define CHUNK   4
#define XSTRIDE 36                      // 34 cols padded to 36
#define XBUF    (CHUNK * 34 * XSTRIDE)  // floats per stage = 4896
#define STAGES  3
#define NCO     8
#define T_STEPS 8
#define BATCH   16
#define CIN     64
#define COUT    128
#define HW      64
#define NCHUNKS (T_STEPS * 16)          // 128

typedef unsigned long long ull;

__device__ __forceinline__ ull pk2(float lo, float hi) {
    ull r; asm("mov.b64 %0, {%1, %2};" : "=l"(r) : "f"(lo), "f"(hi)); return r;
}
__device__ __forceinline__ void upk2(ull a, float& lo, float& hi) {
    asm("mov.b64 {%0, %1}, %2;" : "=f"(lo), "=f"(hi) : "l"(a));
}
__device__ __forceinline__ void ffma2(ull& d, ull a, ull b) {
    asm("fma.rn.f32x2 %0, %1, %2, %0;" : "+l"(d) : "l"(a), "l"(b));
}
__device__ __forceinline__ void cp4(unsigned dst, const float* src, unsigned sz) {
    asm volatile("cp.async.ca.shared.global [%0], [%1], 4, %2;"
                 :: "r"(dst), "l"(src), "r"(sz));
}
__device__ __forceinline__ void cp_commit() {
    asm volatile("cp.async.commit_group;");
}
__device__ __forceinline__ void cp_wait1() {
    asm volatile("cp.async.wait_group 1;");   // newest group may stay in flight
}

__global__ __launch_bounds__(THREADS, 2)
void convlif_kernel(const float* __restrict__ x,
                    const float* __restrict__ w,
                    float* __restrict__ out)
{
    extern __shared__ float smem[];
    // layout: xs[STAGES][XBUF] | ws [NCO][CIN][10] {w,w} pairs
    ull* ws = (ull*)(smem + STAGES * XBUF);

    const int tid  = threadIdx.x;
    const int lane = tid & 31;
    const int warp = tid >> 5;
    const int tx   = tid & 7;        // col-group: 4 pixels at w0 + 4*tx
    const int ty   = tid >> 3;       // row within tile: 0..31
    const int h0   = (blockIdx.x >> 1) * 32;
    const int w0   = (blockIdx.x & 1) * 32;
    const int b    = blockIdx.y;
    const int cg   = blockIdx.z;

    // Weights -> smem as {w,w} pairs (80B rows, 16B aligned). Visible to all
    // threads after the first __syncthreads inside the main loop (g=0).
    {
        const float* wg = w + (size_t)cg * NCO * CIN * 9;
        for (int i = tid; i < NCO * CIN * 9; i += THREADS) {
            int cocin = i / 9, k = i - cocin * 9;
            float wv = wg[i];
            ws[cocin * 10 + k] = pk2(wv, wv);
        }
    }

    // Loader geometry (division-free): warp covers channel c = warp>>1 and 17
    // rows starting at (warp&1)*17; lane covers col = lane (+ lanes 0/1: 32/33).
    const int lc    = warp >> 1;
    const int lrow0 = (warp & 1) * 17;
    const int gw_m  = w0 + lane - 1;
    const unsigned okw_m = ((unsigned)gw_m < HW) ? 4u : 0u;
    const int gwc_m = (gw_m < 0) ? 0 : (gw_m >= HW ? HW - 1 : gw_m);
    const int gw_t  = w0 + 32 + lane - 1;
    const unsigned okw_t = ((unsigned)gw_t < HW) ? 4u : 0u;
    const int gwc_t = (gw_t >= HW) ? HW - 1 : gw_t;

    unsigned smem_u32;
    {
        void* p = smem;
        asm("{ .reg .u64 t; cvta.to.shared.u64 t, %1; cvt.u32.u64 %0, t; }"
            : "=r"(smem_u32) : "l"(p));
    }

    // Prefetch chunk g into stage s.
    auto prefetch = [&](int g, int s) {
        if (g < NCHUNKS) {
            const int t  = g >> 4;
            const int ch = g & 15;
            const float* xb = x + (((size_t)t * BATCH + b) * CIN + ch * CHUNK + lc) * (HW * HW);
            unsigned dst0 = smem_u32 + (unsigned)(s * XBUF + lc * 34 * XSTRIDE) * 4u;
#pragma unroll 1
            for (int j = 0; j < 17; j++) {
                const int row = lrow0 + j;
                const int gh  = h0 + row - 1;
                const unsigned okh = ((unsigned)gh < HW) ? 4u : 0u;
                const int ghc = (gh < 0) ? 0 : (gh >= HW ? HW - 1 : gh);
                const float* srow = xb + ghc * HW;
                unsigned drow = dst0 + (unsigned)(row * XSTRIDE) * 4u;
                cp4(drow + (unsigned)lane * 4u, srow + gwc_m, okh & okw_m);
                if (lane < 2)
                    cp4(drow + (unsigned)(32 + lane) * 4u, srow + gwc_t, okh & okw_t);
            }
        }
        cp_commit();
    };

    // Prologue: chunks 0 and 1 into stages 0 and 1.
    prefetch(0, 0);
    prefetch(1, 1);

    ull v01[NCO], v23[NCO], a01[NCO], a23[NCO];
#pragma unroll
    for (int co = 0; co < NCO; co++) {
        v01[co] = 0ull; v23[co] = 0ull;
        a01[co] = 0ull; a23[co] = 0ull;
    }

    int buf = 0;    // consumer stage for chunk g
    int nbuf = 2;   // producer stage for chunk g+2

#pragma unroll 1
    for (int g = 0; g < NCHUNKS; g++) {
        cp_wait1();            // group g complete (g+1 may stay in flight)
        __syncthreads();       // all threads see chunk g; stage nbuf free

        prefetch(g + 2, nbuf);
        nbuf = (nbuf == STAGES - 1) ? 0 : nbuf + 1;

        const float* xs = smem + buf * XBUF;
        const int cin0 = (g & 15) * CHUNK;

#pragma unroll 1
        for (int c = 0; c < CHUNK; c++) {
            const float* xr = xs + (c * 34 + ty) * XSTRIDE + tx * 4;
            ull P[3][5];
#pragma unroll
            for (int dy = 0; dy < 3; dy++) {
                float4 a4 = *(const float4*)(xr + dy * XSTRIDE);
                float2 b2 = *(const float2*)(xr + dy * XSTRIDE + 4);
                P[dy][0] = pk2(a4.x, a4.y);
                P[dy][1] = pk2(a4.y, a4.z);
                P[dy][2] = pk2(a4.z, a4.w);
                P[dy][3] = pk2(a4.w, b2.x);
                P[dy][4] = pk2(b2.x, b2.y);
            }
            const int cin = cin0 + c;
#pragma unroll
            for (int co = 0; co < NCO; co++) {
                const ull* wp = ws + (co * CIN + cin) * 10;
                ull wq[9];
#pragma unroll
                for (int k = 0; k < 9; k++) wq[k] = wp[k];
#pragma unroll
                for (int ky = 0; ky < 3; ky++)
#pragma unroll
                    for (int kx = 0; kx < 3; kx++) {
                        ffma2(a01[co], P[ky][kx],     wq[ky * 3 + kx]);
                        ffma2(a23[co], P[ky][kx + 2], wq[ky * 3 + kx]);
                    }
            }
        }

        if ((g & 15) == 15) {
            const int t = g >> 4;
            // LIF update + spike store (reference op order: v += (z - v)/2).
#pragma unroll
            for (int co = 0; co < NCO; co++) {
                float z0, z1, z2, z3, u0, u1, u2, u3;
                upk2(a01[co], z0, z1);
                upk2(a23[co], z2, z3);
                upk2(v01[co], u0, u1);
                upk2(v23[co], u2, u3);
                u0 += (z0 - u0) * 0.5f;
                u1 += (z1 - u1) * 0.5f;
                u2 += (z2 - u2) * 0.5f;
                u3 += (z3 - u3) * 0.5f;
                float4 s;
                s.x = (u0 >= 1.0f) ? 1.f : 0.f;  if (u0 >= 1.0f) u0 = 0.f;
                s.y = (u1 >= 1.0f) ? 1.f : 0.f;  if (u1 >= 1.0f) u1 = 0.f;
                s.z = (u2 >= 1.0f) ? 1.f : 0.f;  if (u2 >= 1.0f) u2 = 0.f;
                s.w = (u3 >= 1.0f) ? 1.f : 0.f;  if (u3 >= 1.0f) u3 = 0.f;
                v01[co] = pk2(u0, u1);
                v23[co] = pk2(u2, u3);
                a01[co] = 0ull;
                a23[co] = 0ull;
                size_t o = ((((size_t)t * BATCH + b) * COUT + cg * NCO + co) * HW + (h0 + ty)) * HW
                         + (w0 + tx * 4);
                *(float4*)(out + o) = s;
            }
        }

        buf = (buf == STAGES - 1) ? 0 : buf + 1;
    }
}

extern "C" void kernel_launch(void* const* d_in, const int* in_sizes, int n_in,
                              void* d_out, int out_size)
{
    const float* x = (const float*)d_in[0];
    const float* w = (const float*)d_in[1];
    float* out     = (float*)d_out;

    const int smem_bytes = STAGES * XBUF * 4   // x ring: 58,752 B
                         + NCO * CIN * 10 * 8; // weight pairs: 40,960 B -> 99,712 B
    cudaFuncSetAttribute(convlif_kernel,
                         cudaFuncAttributeMaxDynamicSharedMemorySize, smem_bytes);

    dim3 grid(4 /* 2x2 spatial tiles */, BATCH, COUT / NCO);
    convlif_kernel<<<grid, THREADS, smem_bytes>>>(x, w, out);
}

// round 16
// speedup vs baseline: 1.2956x; 1.2956x over previous
#include <cuda_runtime.h>

// StatelessConvLIF: fused 3x3 SAME conv (fp32) + LIF scan over T=8.
// x: [8,16,64,64,64] fp32, W: [128,64,3,3] fp32, out spikes: [8,16,128,64,64] fp32.
//
// R16: co-pair lane packing. FFMA2 lanes now hold {co_even, co_odd} so the
// weight operand is a pair of DISTINCT weights (no {w,w} duplication):
// weight smem halves, broadcast weight LDS per cin drops 40 -> 24 wavefronts
// (R15 ncu: weight broadcasts were ~64% of smem crossbar at L1=68.9%), and
// the x operand becomes a {x,x} splat. ky-outer loop keeps live set ~100 regs
// (was 120) so ptxas can overlap LDS under FFMA2. Per-output tap accumulation
// order (cin asc, ky asc, kx asc) is IDENTICAL -> rel_err must stay 7.0777e-4.
// Keeps R14's 3-stage cp.async ring with wait_group 1.

#define THREADS 256
#define CHUNK   4
#define XSTRIDE 36                      // 34 cols padded to 36
#define XBUF    (CHUNK * 34 * XSTRIDE)  // floats per stage = 4896
#define STAGES  3
#define NCO     8                       // couts per block (4 co-pairs)
#define T_STEPS 8
#define BATCH   16
#define CIN     64
#define COUT    128
#define HW      64
#define NCHUNKS (T_STEPS * 16)          // 128
// weight smem: [cin][ky][cp][4] pairs (tap 3 = pad); 64*3*16 pairs * 8B
#define WS_PAIRS (CIN * 3 * 16)

typedef unsigned long long ull;

__device__ __forceinline__ ull pk2(float lo, float hi) {
    ull r; asm("mov.b64 %0, {%1, %2};" : "=l"(r) : "f"(lo), "f"(hi)); return r;
}
__device__ __forceinline__ void upk2(ull a, float& lo, float& hi) {
    asm("mov.b64 {%0, %1}, %2;" : "=f"(lo), "=f"(hi) : "l"(a));
}
__device__ __forceinline__ void ffma2(ull& d, ull a, ull b) {
    asm("fma.rn.f32x2 %0, %1, %2, %0;" : "+l"(d) : "l"(a), "l"(b));
}
__device__ __forceinline__ void cp4(unsigned dst, const float* src, unsigned sz) {
    asm volatile("cp.async.ca.shared.global [%0], [%1], 4, %2;"
                 :: "r"(dst), "l"(src), "r"(sz));
}
__device__ __forceinline__ void cp_commit() {
    asm volatile("cp.async.commit_group;");
}
__device__ __forceinline__ void cp_wait1() {
    asm volatile("cp.async.wait_group 1;");   // newest group may stay in flight
}

__global__ __launch_bounds__(THREADS, 2)
void convlif_kernel(const float* __restrict__ x,
                    const float* __restrict__ w,
                    float* __restrict__ out)
{
    extern __shared__ float smem[];
    // layout: xs[STAGES][XBUF] | ws[cin][ky][cp][4] co-pair weight pairs
    ull* ws = (ull*)(smem + STAGES * XBUF);

    const int tid  = threadIdx.x;
    const int lane = tid & 31;
    const int warp = tid >> 5;
    const int tx   = tid & 7;        // col-group: 4 pixels at w0 + 4*tx
    const int ty   = tid >> 3;       // row within tile: 0..31
    const int h0   = (blockIdx.x >> 1) * 32;
    const int w0   = (blockIdx.x & 1) * 32;
    const int b    = blockIdx.y;
    const int cg   = blockIdx.z;

    // Weights -> smem as {w[2cp], w[2cp+1]} pairs, layout [cin][ky][cp][4].
    {
        const float* wg = w + (size_t)cg * NCO * CIN * 9;
        for (int i = tid; i < CIN * 3 * 4 * 3; i += THREADS) {   // 2304 entries
            int cin = i / 36;  int r  = i - cin * 36;
            int ky  = r / 12;  int r2 = r - ky * 12;
            int cp  = r2 / 3;  int tap = r2 - cp * 3;
            float we = wg[(2 * cp)     * CIN * 9 + cin * 9 + ky * 3 + tap];
            float wo = wg[(2 * cp + 1) * CIN * 9 + cin * 9 + ky * 3 + tap];
            ws[((cin * 3 + ky) * 4 + cp) * 4 + tap] = pk2(we, wo);
        }
    }

    // Loader geometry (division-free): warp covers channel c = warp>>1 and 17
    // rows starting at (warp&1)*17; lane covers col = lane (+ lanes 0/1: 32/33).
    const int lc    = warp >> 1;
    const int lrow0 = (warp & 1) * 17;
    const int gw_m  = w0 + lane - 1;
    const unsigned okw_m = ((unsigned)gw_m < HW) ? 4u : 0u;
    const int gwc_m = (gw_m < 0) ? 0 : (gw_m >= HW ? HW - 1 : gw_m);
    const int gw_t  = w0 + 32 + lane - 1;
    const unsigned okw_t = ((unsigned)gw_t < HW) ? 4u : 0u;
    const int gwc_t = (gw_t >= HW) ? HW - 1 : gw_t;

    unsigned smem_u32;
    {
        void* p = smem;
        asm("{ .reg .u64 t; cvta.to.shared.u64 t, %1; cvt.u32.u64 %0, t; }"
            : "=r"(smem_u32) : "l"(p));
    }

    // Prefetch chunk g into stage s.
    auto prefetch = [&](int g, int s) {
        if (g < NCHUNKS) {
            const int t  = g >> 4;
            const int ch = g & 15;
            const float* xb = x + (((size_t)t * BATCH + b) * CIN + ch * CHUNK + lc) * (HW * HW);
            unsigned dst0 = smem_u32 + (unsigned)(s * XBUF + lc * 34 * XSTRIDE) * 4u;
#pragma unroll 1
            for (int j = 0; j < 17; j++) {
                const int row = lrow0 + j;
                const int gh  = h0 + row - 1;
                const unsigned okh = ((unsigned)gh < HW) ? 4u : 0u;
                const int ghc = (gh < 0) ? 0 : (gh >= HW ? HW - 1 : gh);
                const float* srow = xb + ghc * HW;
                unsigned drow = dst0 + (unsigned)(row * XSTRIDE) * 4u;
                cp4(drow + (unsigned)lane * 4u, srow + gwc_m, okh & okw_m);
                if (lane < 2)
                    cp4(drow + (unsigned)(32 + lane) * 4u, srow + gwc_t, okh & okw_t);
            }
        }
        cp_commit();
    };

    // Prologue: chunks 0 and 1 into stages 0 and 1.
    prefetch(0, 0);
    prefetch(1, 1);

    // A[cp][px] = conv accumulator pair {o(px, 2cp), o(px, 2cp+1)}
    // V[cp][px] = membrane potential, same packing.
    ull A[4][4], V[4][4];
#pragma unroll
    for (int cp = 0; cp < 4; cp++)
#pragma unroll
        for (int px = 0; px < 4; px++) { A[cp][px] = 0ull; V[cp][px] = 0ull; }

    int buf = 0;    // consumer stage for chunk g
    int nbuf = 2;   // producer stage for chunk g+2

#pragma unroll 1
    for (int g = 0; g < NCHUNKS; g++) {
        cp_wait1();            // group g complete (g+1 may stay in flight)
        __syncthreads();       // all threads see chunk g; stage nbuf free

        prefetch(g + 2, nbuf);
        nbuf = (nbuf == STAGES - 1) ? 0 : nbuf + 1;

        const float* xs = smem + buf * XBUF;
        const int cin0 = (g & 15) * CHUNK;

#pragma unroll 1
        for (int c = 0; c < CHUNK; c++) {
            const float* xr = xs + (c * 34 + ty) * XSTRIDE + tx * 4;
            const ull* wrow = ws + (size_t)(cin0 + c) * 48;   // [ky][cp][4]
#pragma unroll
            for (int ky = 0; ky < 3; ky++) {
                float4 a4 = *(const float4*)(xr + ky * XSTRIDE);
                float2 b2 = *(const float2*)(xr + ky * XSTRIDE + 4);
                ull S0 = pk2(a4.x, a4.x);
                ull S1 = pk2(a4.y, a4.y);
                ull S2 = pk2(a4.z, a4.z);
                ull S3 = pk2(a4.w, a4.w);
                ull S4 = pk2(b2.x, b2.x);
                ull S5 = pk2(b2.y, b2.y);
                const ull* wk = wrow + ky * 16;
#pragma unroll
                for (int cp = 0; cp < 4; cp++) {
                    ulonglong2 w01 = *(const ulonglong2*)(wk + cp * 4); // taps 0,1
                    ull w2 = wk[cp * 4 + 2];                            // tap 2
                    // kx = 0
                    ffma2(A[cp][0], S0, w01.x);
                    ffma2(A[cp][1], S1, w01.x);
                    ffma2(A[cp][2], S2, w01.x);
                    ffma2(A[cp][3], S3, w01.x);
                    // kx = 1
                    ffma2(A[cp][0], S1, w01.y);
                    ffma2(A[cp][1], S2, w01.y);
                    ffma2(A[cp][2], S3, w01.y);
                    ffma2(A[cp][3], S4, w01.y);
                    // kx = 2
                    ffma2(A[cp][0], S2, w2);
                    ffma2(A[cp][1], S3, w2);
                    ffma2(A[cp][2], S4, w2);
                    ffma2(A[cp][3], S5, w2);
                }
            }
        }

        if ((g & 15) == 15) {
            const int t = g >> 4;
            // LIF update + spike store (reference op order: v += (z - v)/2).
#pragma unroll
            for (int cp = 0; cp < 4; cp++) {
                float ze[4], zo[4], ue[4], uo[4];
#pragma unroll
                for (int px = 0; px < 4; px++) {
                    upk2(A[cp][px], ze[px], zo[px]);
                    upk2(V[cp][px], ue[px], uo[px]);
                }
                float4 se, so;
                ue[0] += (ze[0] - ue[0]) * 0.5f;
                ue[1] += (ze[1] - ue[1]) * 0.5f;
                ue[2] += (ze[2] - ue[2]) * 0.5f;
                ue[3] += (ze[3] - ue[3]) * 0.5f;
                uo[0] += (zo[0] - uo[0]) * 0.5f;
                uo[1] += (zo[1] - uo[1]) * 0.5f;
                uo[2] += (zo[2] - uo[2]) * 0.5f;
                uo[3] += (zo[3] - uo[3]) * 0.5f;
                se.x = (ue[0] >= 1.0f) ? 1.f : 0.f;  if (ue[0] >= 1.0f) ue[0] = 0.f;
                se.y = (ue[1] >= 1.0f) ? 1.f : 0.f;  if (ue[1] >= 1.0f) ue[1] = 0.f;
                se.z = (ue[2] >= 1.0f) ? 1.f : 0.f;  if (ue[2] >= 1.0f) ue[2] = 0.f;
                se.w = (ue[3] >= 1.0f) ? 1.f : 0.f;  if (ue[3] >= 1.0f) ue[3] = 0.f;
                so.x = (uo[0] >= 1.0f) ? 1.f : 0.f;  if (uo[0] >= 1.0f) uo[0] = 0.f;
                so.y = (uo[1] >= 1.0f) ? 1.f : 0.f;  if (uo[1] >= 1.0f) uo[1] = 0.f;
                so.z = (uo[2] >= 1.0f) ? 1.f : 0.f;  if (uo[2] >= 1.0f) uo[2] = 0.f;
                so.w = (uo[3] >= 1.0f) ? 1.f : 0.f;  if (uo[3] >= 1.0f) uo[3] = 0.f;
#pragma unroll
                for (int px = 0; px < 4; px++) {
                    V[cp][px] = pk2(ue[px], uo[px]);
                    A[cp][px] = 0ull;
                }
                const size_t base = (((size_t)t * BATCH + b) * COUT + cg * NCO + 2 * cp);
                size_t oe = ((base)     * HW + (h0 + ty)) * HW + (w0 + tx * 4);
                size_t oo = ((base + 1) * HW + (h0 + ty)) * HW + (w0 + tx * 4);
                *(float4*)(out + oe) = se;
                *(float4*)(out + oo) = so;
            }
        }

        buf = (buf == STAGES - 1) ? 0 : buf + 1;
    }
}

extern "C" void kernel_launch(void* const* d_in, const int* in_sizes, int n_in,
                              void* d_out, int out_size)
{
    const float* x = (const float*)d_in[0];
    const float* w = (const float*)d_in[1];
    float* out     = (float*)d_out;

    const int smem_bytes = STAGES * XBUF * 4   // x ring: 58,752 B
                         + WS_PAIRS * 8;       // weights: 24,576 B -> 83,328 B
    cudaFuncSetAttribute(convlif_kernel,
                         cudaFuncAttributeMaxDynamicSharedMemorySize, smem_bytes);

    dim3 grid(4 /* 2x2 spatial tiles */, BATCH, COUT / NCO);
    convlif_kernel<<<grid, THREADS, smem_bytes>>>(x, w, out);
}